// round 12
// baseline (speedup 1.0000x reference)
#include <cuda_runtime.h>

// Problem constants
#define NB   8
#define CC   16
#define LQ   1024
#define DD   7
#define HH   16
#define SZ   112          // CC*DD == HH*DD

typedef unsigned long long ull;

// Scratch (allocation-free rule: __device__ globals)
__device__ float g_q[NB * HH * LQ * DD];
__device__ float g_k[NB * HH * LQ * DD];
__device__ float g_v[NB * HH * LQ * DD];

// ---------------- f32x2 packed helpers (sm_103a) ----------------
__device__ __forceinline__ ull pack2(float lo, float hi) {
    ull r; asm("mov.b64 %0, {%1, %2};" : "=l"(r) : "f"(lo), "f"(hi)); return r;
}
__device__ __forceinline__ void unpack2(ull v, float &lo, float &hi) {
    asm("mov.b64 {%0, %1}, %2;" : "=f"(lo), "=f"(hi) : "l"(v));
}
__device__ __forceinline__ ull ffma2(ull a, ull b, ull c) {
    ull d; asm("fma.rn.f32x2 %0, %1, %2, %3;" : "=l"(d) : "l"(a), "l"(b), "l"(c)); return d;
}
__device__ __forceinline__ ull fmul2(ull a, ull b) {
    ull d; asm("mul.rn.f32x2 %0, %1, %2;" : "=l"(d) : "l"(a), "l"(b)); return d;
}
__device__ __forceinline__ ull fadd2(ull a, ull b) {
    ull d; asm("add.rn.f32x2 %0, %1, %2;" : "=l"(d) : "l"(a), "l"(b)); return d;
}
__device__ __forceinline__ float ex2f(float x) {
    float y; asm("ex2.approx.ftz.f32 %0, %1;" : "=f"(y) : "f"(x)); return y;
}

// ---------------------------------------------------------------
// Kernel A: fused transpose + QKV projection, f32x2 packed math.
// xf[n,l,c*7+d] = x[n,c,l,d];  q[n,l,j] = sum_i xf[n,l,i]*W[j,i] + b[j]
//
// W staged TRANSPOSED in SMEM (Wt[k][j], j contiguous) so one LDS.64
// (full-warp broadcast: address independent of lane) delivers a ready-
// packed {W[j,k], W[j+1,k]} f32x2 operand. Inner loop per k per thread:
// 1 LDS.32 + 1 dup-MOV + 7 LDS.64 + 7 FFMA2 (vs 15 LDS + 14 FFMA scalar).
// Output written directly in [N,H,L,7] head-split layout.
// grid: (256 row-tiles of 32, 3 for q/k/v), block 256.
// ---------------------------------------------------------------
__global__ void __launch_bounds__(256) qkv_kernel(
    const float* __restrict__ x,
    const float* __restrict__ Wq, const float* __restrict__ bq,
    const float* __restrict__ Wk, const float* __restrict__ bk,
    const float* __restrict__ Wv, const float* __restrict__ bv)
{
    extern __shared__ float sm[];
    float* xs = sm;                    // [32][113]  (odd stride: conflict-free)
    float* Wt = sm + 32 * 113;         // [112][114] transposed (even stride: 8B align)
    float* bs = Wt + SZ * 114;         // [112]

    const float* W; const float* bias; float* dst;
    int which = blockIdx.y;
    if (which == 0)      { W = Wq; bias = bq; dst = g_q; }
    else if (which == 1) { W = Wk; bias = bk; dst = g_k; }
    else                 { W = Wv; bias = bv; dst = g_v; }

    int tile = blockIdx.x;             // 0..255; 32 | 1024 so tiles never cross n
    int n  = (tile * 32) / LQ;
    int l0 = (tile * 32) % LQ;
    int tid = threadIdx.x;

    // Stage x tile [32 rows][112], building the [N,L,C*D] transpose on the fly.
    const float* xb = x + (size_t)n * CC * LQ * DD;
    for (int idx = tid; idx < 32 * SZ; idx += 256) {
        int c   = idx / (32 * DD);
        int rem = idx % (32 * DD);
        int r   = rem / DD;
        int dd  = rem % DD;
        xs[r * 113 + c * DD + dd] = xb[c * LQ * DD + (l0 + r) * DD + dd];
    }
    // Stage W transposed: Wt[k][j] = W[j][k]  (coalesced GMEM read)
    for (int idx = tid; idx < SZ * SZ; idx += 256) {
        int j = idx / SZ;
        int k = idx % SZ;
        Wt[k * 114 + j] = W[idx];
    }
    if (tid < SZ) bs[tid] = bias[tid];
    __syncthreads();

    int r  = tid & 31;                 // row within tile (warp = 32 rows)
    int jj = tid >> 5;                 // output group: pairs jj*14+2o, +1

    ull acc[7];
#pragma unroll
    for (int o = 0; o < 7; o++)
        acc[o] = pack2(bs[jj * 14 + 2 * o], bs[jj * 14 + 2 * o + 1]);

#pragma unroll 4
    for (int k = 0; k < SZ; k++) {
        float xv = xs[r * 113 + k];    // conflict-free (odd stride)
        ull xv2 = pack2(xv, xv);
        const ull* wrow = reinterpret_cast<const ull*>(Wt + k * 114 + jj * 14);
#pragma unroll
        for (int o = 0; o < 7; o++)    // full-warp broadcast LDS.64
            acc[o] = ffma2(xv2, wrow[o], acc[o]);
    }

    int l = l0 + r;
#pragma unroll
    for (int o = 0; o < 7; o++) {
        int j0 = jj * 14 + 2 * o;
        float a0, a1;
        unpack2(acc[o], a0, a1);
        dst[((size_t)(n * HH + j0 / DD) * LQ + l) * DD + (j0 % DD)] = a0;
        int j1 = j0 + 1;
        dst[((size_t)(n * HH + j1 / DD) * LQ + l) * DD + (j1 % DD)] = a1;
    }
}

// ---------------------------------------------------------------
// Kernel B: fused attention, one CTA per (n,h); full K,V in SMEM.
// K and V staged DUPLICATED: row j = {k0,k0,...,k6,k6,pad,pad} (64B)
// so LDS.128 broadcast yields ready-packed {k,k} f32x2 operands.
// Each thread owns 4 query rows as 2 packed row-pairs -> all math is
// FFMA2 (2x fp32 rate). Softmax without max-subtraction (|score|<=~1,
// overflow-impossible, algebraically identical): p = exp2(s*log2e/32),
// constant folded into q at load. Single pass, no score matrix in HBM.
// FMA-pipe-bound: 60 FFMA2/SMSP/j -> ~120 cyc/j -> ~62us over 128 CTAs.
// ---------------------------------------------------------------
__global__ void __launch_bounds__(256, 1) attn_kernel(float* __restrict__ out)
{
    extern __shared__ float sm[];
    float* Kd = sm;                    // [1024][16] duplicated
    float* Vd = sm + LQ * 16;          // [1024][16] duplicated

    int nh  = blockIdx.x;
    int tid = threadIdx.x;

    const float* Kb = g_k + (size_t)nh * LQ * DD;
    const float* Vb = g_v + (size_t)nh * LQ * DD;

    float2* Kd2 = reinterpret_cast<float2*>(Kd);
    float2* Vd2 = reinterpret_cast<float2*>(Vd);
    for (int i = tid; i < LQ * DD; i += 256) {
        int j  = i / DD;
        int dd = i - j * DD;
        float kv = Kb[i];
        float vv = Vb[i];
        Kd2[j * 8 + dd] = make_float2(kv, kv);
        Vd2[j * 8 + dd] = make_float2(vv, vv);
    }
    __syncthreads();

    const float Cs = 0.0450842227f;    // log2(e) / sqrt(1024)

    int r0 = tid * 4;                  // this thread's 4 query rows
    const float* Qb = g_q + (size_t)nh * LQ * DD + (size_t)r0 * DD;

    ull qa[7], qb[7], acca[7], accb[7];
#pragma unroll
    for (int dd = 0; dd < 7; dd++) {
        qa[dd] = pack2(Qb[dd]      * Cs, Qb[DD + dd]     * Cs);
        qb[dd] = pack2(Qb[2*DD+dd] * Cs, Qb[3*DD + dd]   * Cs);
        acca[dd] = 0ull;               // {+0.f, +0.f}
        accb[dd] = 0ull;
    }
    ull ssa = 0ull, ssb = 0ull;

#pragma unroll 4
    for (int j = 0; j < LQ; j++) {
        const ulonglong2* kr = reinterpret_cast<const ulonglong2*>(Kd + j * 16);
        const ulonglong2* vr = reinterpret_cast<const ulonglong2*>(Vd + j * 16);
        ulonglong2 k01 = kr[0], k23 = kr[1], k45 = kr[2], k6p = kr[3];

        // dots for both row-pairs (14 FFMA2-equivalents)
        ull da = fmul2(qa[0], k01.x);
        ull db = fmul2(qb[0], k01.x);
        da = ffma2(qa[1], k01.y, da);  db = ffma2(qb[1], k01.y, db);
        da = ffma2(qa[2], k23.x, da);  db = ffma2(qb[2], k23.x, db);
        da = ffma2(qa[3], k23.y, da);  db = ffma2(qb[3], k23.y, db);
        da = ffma2(qa[4], k45.x, da);  db = ffma2(qb[4], k45.x, db);
        da = ffma2(qa[5], k45.y, da);  db = ffma2(qb[5], k45.y, db);
        da = ffma2(qa[6], k6p.x, da);  db = ffma2(qb[6], k6p.x, db);

        float s0, s1, s2, s3;
        unpack2(da, s0, s1);
        unpack2(db, s2, s3);
        ull pa = pack2(ex2f(s0), ex2f(s1));
        ull pb = pack2(ex2f(s2), ex2f(s3));
        ssa = fadd2(ssa, pa);
        ssb = fadd2(ssb, pb);

        ulonglong2 v01 = vr[0], v23 = vr[1], v45 = vr[2], v6p = vr[3];
        acca[0] = ffma2(pa, v01.x, acca[0]);  accb[0] = ffma2(pb, v01.x, accb[0]);
        acca[1] = ffma2(pa, v01.y, acca[1]);  accb[1] = ffma2(pb, v01.y, accb[1]);
        acca[2] = ffma2(pa, v23.x, acca[2]);  accb[2] = ffma2(pb, v23.x, accb[2]);
        acca[3] = ffma2(pa, v23.y, acca[3]);  accb[3] = ffma2(pb, v23.y, accb[3]);
        acca[4] = ffma2(pa, v45.x, acca[4]);  accb[4] = ffma2(pb, v45.x, accb[4]);
        acca[5] = ffma2(pa, v45.y, acca[5]);  accb[5] = ffma2(pb, v45.y, accb[5]);
        acca[6] = ffma2(pa, v6p.x, acca[6]);  accb[6] = ffma2(pb, v6p.x, accb[6]);
    }

    // Epilogue: normalize and store [N,H,L,7]
    float sa0, sa1, sb0, sb1;
    unpack2(ssa, sa0, sa1);
    unpack2(ssb, sb0, sb1);
    float i0 = 1.0f / sa0, i1 = 1.0f / sa1, i2 = 1.0f / sb0, i3 = 1.0f / sb1;

    float* ob = out + (size_t)nh * LQ * DD + (size_t)r0 * DD;
#pragma unroll
    for (int dd = 0; dd < 7; dd++) {
        float a0, a1, b0, b1;
        unpack2(acca[dd], a0, a1);
        unpack2(accb[dd], b0, b1);
        ob[dd]          = a0 * i0;
        ob[DD + dd]     = a1 * i1;
        ob[2 * DD + dd] = b0 * i2;
        ob[3 * DD + dd] = b1 * i3;
    }
}

// ---------------------------------------------------------------
extern "C" void kernel_launch(void* const* d_in, const int* in_sizes, int n_in,
                              void* d_out, int out_size)
{
    const float* x  = (const float*)d_in[0];
    const float* Wq = (const float*)d_in[1];
    const float* bq = (const float*)d_in[2];
    const float* Wk = (const float*)d_in[3];
    const float* bk = (const float*)d_in[4];
    const float* Wv = (const float*)d_in[5];
    const float* bv = (const float*)d_in[6];
    float* out = (float*)d_out;

    const int SMEM_A = (32 * 113 + SZ * 114 + SZ) * (int)sizeof(float);  // 65984 B
    const int SMEM_B = 2 * LQ * 16 * (int)sizeof(float);                 // 131072 B

    cudaFuncSetAttribute(qkv_kernel,  cudaFuncAttributeMaxDynamicSharedMemorySize, SMEM_A);
    cudaFuncSetAttribute(attn_kernel, cudaFuncAttributeMaxDynamicSharedMemorySize, SMEM_B);

    dim3 gA((NB * LQ) / 32, 3, 1);     // 256 x 3
    qkv_kernel<<<gA, 256, SMEM_A>>>(x, Wq, bq, Wk, bk, Wv, bv);

    attn_kernel<<<NB * HH, 256, SMEM_B>>>(out);   // 128 CTAs
}

// round 15
// speedup vs baseline: 1.0761x; 1.0761x over previous
#include <cuda_runtime.h>

// Problem constants
#define NB   8
#define CC   16
#define LQ   1024
#define DD   7
#define HH   16
#define SZ   112          // CC*DD == HH*DD

typedef unsigned long long ull;

// Scratch (allocation-free rule: __device__ globals)
__device__ float g_q[NB * HH * LQ * DD];
__device__ float g_k[NB * HH * LQ * DD];
__device__ float g_v[NB * HH * LQ * DD];

// ---------------- f32x2 packed helpers (sm_103a) ----------------
__device__ __forceinline__ ull pack2(float lo, float hi) {
    ull r; asm("mov.b64 %0, {%1, %2};" : "=l"(r) : "f"(lo), "f"(hi)); return r;
}
__device__ __forceinline__ void unpack2(ull v, float &lo, float &hi) {
    asm("mov.b64 {%0, %1}, %2;" : "=f"(lo), "=f"(hi) : "l"(v));
}
__device__ __forceinline__ ull ffma2(ull a, ull b, ull c) {
    ull d; asm("fma.rn.f32x2 %0, %1, %2, %3;" : "=l"(d) : "l"(a), "l"(b), "l"(c)); return d;
}
__device__ __forceinline__ ull fmul2(ull a, ull b) {
    ull d; asm("mul.rn.f32x2 %0, %1, %2;" : "=l"(d) : "l"(a), "l"(b)); return d;
}
__device__ __forceinline__ ull fadd2(ull a, ull b) {
    ull d; asm("add.rn.f32x2 %0, %1, %2;" : "=l"(d) : "l"(a), "l"(b)); return d;
}
__device__ __forceinline__ float ex2f(float x) {
    float y; asm("ex2.approx.ftz.f32 %0, %1;" : "=f"(y) : "f"(x)); return y;
}

// ---------------------------------------------------------------
// Kernel A: fused transpose + QKV projection, f32x2 packed math.
// MERGED: one CTA computes q, k AND v for its 32-row tile (x staged
// once, W re-staged per phase) -> 256 CTAs, single wave at 3 CTAs/SM
// (old: 768 CTAs = 2 waves over ~444 slots).
// ---------------------------------------------------------------
__global__ void __launch_bounds__(256) qkv_kernel(
    const float* __restrict__ x,
    const float* __restrict__ Wq, const float* __restrict__ bq,
    const float* __restrict__ Wk, const float* __restrict__ bk,
    const float* __restrict__ Wv, const float* __restrict__ bv)
{
    extern __shared__ float sm[];
    float* xs = sm;                    // [32][113]  (odd stride: conflict-free)
    float* Wt = sm + 32 * 113;         // [112][114] transposed (8B-aligned pairs)
    float* bs = Wt + SZ * 114;         // [112]

    int tile = blockIdx.x;             // 0..255; 32 | 1024 so tiles never cross n
    int n  = (tile * 32) / LQ;
    int l0 = (tile * 32) % LQ;
    int tid = threadIdx.x;

    // Stage x tile [32 rows][112] once, building [N,L,C*D] transpose.
    const float* xb = x + (size_t)n * CC * LQ * DD;
    for (int idx = tid; idx < 32 * SZ; idx += 256) {
        int c   = idx / (32 * DD);
        int rem = idx % (32 * DD);
        int r   = rem / DD;
        int dd  = rem % DD;
        xs[r * 113 + c * DD + dd] = xb[c * LQ * DD + (l0 + r) * DD + dd];
    }

    const float* Wm[3]; const float* bm[3]; float* dm[3];
    Wm[0] = Wq; bm[0] = bq; dm[0] = g_q;
    Wm[1] = Wk; bm[1] = bk; dm[1] = g_k;
    Wm[2] = Wv; bm[2] = bv; dm[2] = g_v;

    int r  = tid & 31;                 // row within tile
    int jj = tid >> 5;                 // output group: pairs jj*14+2o, +1
    int l  = l0 + r;

    for (int m = 0; m < 3; m++) {
        __syncthreads();               // xs ready (m=0) / prev phase done reading Wt
        const float* W = Wm[m];
        for (int idx = tid; idx < SZ * SZ; idx += 256) {
            int j = idx / SZ;
            int k = idx % SZ;
            Wt[k * 114 + j] = W[idx];  // transposed stage
        }
        if (tid < SZ) bs[tid] = bm[m][tid];
        __syncthreads();

        ull acc[7];
#pragma unroll
        for (int o = 0; o < 7; o++)
            acc[o] = pack2(bs[jj * 14 + 2 * o], bs[jj * 14 + 2 * o + 1]);

#pragma unroll 4
        for (int k = 0; k < SZ; k++) {
            float xv = xs[r * 113 + k];    // conflict-free (odd stride)
            ull xv2 = pack2(xv, xv);
            const ull* wrow = reinterpret_cast<const ull*>(Wt + k * 114 + jj * 14);
#pragma unroll
            for (int o = 0; o < 7; o++)    // full-warp broadcast LDS.64
                acc[o] = ffma2(xv2, wrow[o], acc[o]);
        }

        float* dst = dm[m];
#pragma unroll
        for (int o = 0; o < 7; o++) {
            int j0 = jj * 14 + 2 * o;
            float a0, a1;
            unpack2(acc[o], a0, a1);
            dst[((size_t)(n * HH + j0 / DD) * LQ + l) * DD + (j0 % DD)] = a0;
            int j1 = j0 + 1;
            dst[((size_t)(n * HH + j1 / DD) * LQ + l) * DD + (j1 % DD)] = a1;
        }
    }
}

// ---------------------------------------------------------------
// Kernel B: fused attention. f32x2 lanes packed over KEY PAIRS:
// SMEM row jp holds {k_2jp[d], k_2jp+1[d]} (64B, no duplication) so
// SMEM = 64KB -> 2 CTAs/SM resident. Grid = 2 CTAs per (n,h), each
// owning 512 query rows (query split: no reduction needed). Busy SMs
// get 16 warps = 4/SMSP (was 2/SMSP) to hide the FFMA2/MUFU chains
// that capped fma-pipe at 49.9% in the R12 profile. q duplicated in
// registers {q,q}; scores for both keys of a pair computed in one
// packed chain; probability pair {p_2jp, p_2jp+1} feeds packed V
// accumulation; the two lanes are summed in the epilogue. Same FMA
// instruction count, 2x the warp-level latency hiding.
// ---------------------------------------------------------------
__global__ void __launch_bounds__(256, 2) attn_kernel(float* __restrict__ out)
{
    extern __shared__ ull smu[];
    ull* sKp = smu;                    // [512][8] key-pair packed (lane pad at [7])
    ull* sVp = smu + 512 * 8;          // [512][8]

    int nh   = blockIdx.x >> 1;
    int half = blockIdx.x & 1;
    int tid  = threadIdx.x;

    const float* Kb = g_k + (size_t)nh * LQ * DD;
    const float* Vb = g_v + (size_t)nh * LQ * DD;

    for (int i = tid; i < 512 * DD; i += 256) {
        int jp = i / DD;
        int d  = i - jp * DD;
        sKp[jp * 8 + d] = pack2(Kb[(2 * jp) * DD + d], Kb[(2 * jp + 1) * DD + d]);
        sVp[jp * 8 + d] = pack2(Vb[(2 * jp) * DD + d], Vb[(2 * jp + 1) * DD + d]);
    }
    __syncthreads();

    const float Cs = 0.0450842227f;    // log2(e) / sqrt(1024)

    int r0 = half * 512 + tid * 2;     // this thread's 2 query rows
    const float* Qb = g_q + (size_t)nh * LQ * DD + (size_t)r0 * DD;

    ull qa[7], qb[7], acA[7], acB[7];
#pragma unroll
    for (int d = 0; d < 7; d++) {
        float va = Qb[d] * Cs;
        float vb = Qb[DD + d] * Cs;
        qa[d] = pack2(va, va);         // duplicated: both key-lanes see same q
        qb[d] = pack2(vb, vb);
        acA[d] = 0ull;
        acB[d] = 0ull;
    }
    ull ssA = 0ull, ssB = 0ull;

#pragma unroll 4
    for (int jp = 0; jp < 512; jp++) {
        const ulonglong2* kr = reinterpret_cast<const ulonglong2*>(sKp + jp * 8);
        ulonglong2 k01 = kr[0], k23 = kr[1], k45 = kr[2], k6p = kr[3];

        // packed dots: lane0 = key 2jp, lane1 = key 2jp+1, for both rows
        ull da = fmul2(qa[0], k01.x);
        ull db = fmul2(qb[0], k01.x);
        da = ffma2(qa[1], k01.y, da);  db = ffma2(qb[1], k01.y, db);
        da = ffma2(qa[2], k23.x, da);  db = ffma2(qb[2], k23.x, db);
        da = ffma2(qa[3], k23.y, da);  db = ffma2(qb[3], k23.y, db);
        da = ffma2(qa[4], k45.x, da);  db = ffma2(qb[4], k45.x, db);
        da = ffma2(qa[5], k45.y, da);  db = ffma2(qb[5], k45.y, db);
        da = ffma2(qa[6], k6p.x, da);  db = ffma2(qb[6], k6p.x, db);
        // k6p.y = pad lane, never used

        float s0, s1, s2, s3;
        unpack2(da, s0, s1);
        unpack2(db, s2, s3);
        ull pa = pack2(ex2f(s0), ex2f(s1));   // {p_2jp, p_2jp+1} row A
        ull pb = pack2(ex2f(s2), ex2f(s3));   // row B
        ssA = fadd2(ssA, pa);
        ssB = fadd2(ssB, pb);

        const ulonglong2* vr = reinterpret_cast<const ulonglong2*>(sVp + jp * 8);
        ulonglong2 v01 = vr[0], v23 = vr[1], v45 = vr[2], v6p = vr[3];
        acA[0] = ffma2(pa, v01.x, acA[0]);  acB[0] = ffma2(pb, v01.x, acB[0]);
        acA[1] = ffma2(pa, v01.y, acA[1]);  acB[1] = ffma2(pb, v01.y, acB[1]);
        acA[2] = ffma2(pa, v23.x, acA[2]);  acB[2] = ffma2(pb, v23.x, acB[2]);
        acA[3] = ffma2(pa, v23.y, acA[3]);  acB[3] = ffma2(pb, v23.y, acB[3]);
        acA[4] = ffma2(pa, v45.x, acA[4]);  acB[4] = ffma2(pb, v45.x, acB[4]);
        acA[5] = ffma2(pa, v45.y, acA[5]);  acB[5] = ffma2(pb, v45.y, acB[5]);
        acA[6] = ffma2(pa, v6p.x, acA[6]);  acB[6] = ffma2(pb, v6p.x, acB[6]);
    }

    // Epilogue: fold key-lanes, normalize, store [N,H,L,7]
    float a0, a1;
    unpack2(ssA, a0, a1);
    float iA = 1.0f / (a0 + a1);
    unpack2(ssB, a0, a1);
    float iB = 1.0f / (a0 + a1);

    float* ob = out + (size_t)nh * LQ * DD + (size_t)r0 * DD;
#pragma unroll
    for (int d = 0; d < 7; d++) {
        unpack2(acA[d], a0, a1);
        ob[d] = (a0 + a1) * iA;
        unpack2(acB[d], a0, a1);
        ob[DD + d] = (a0 + a1) * iB;
    }
}

// ---------------------------------------------------------------
extern "C" void kernel_launch(void* const* d_in, const int* in_sizes, int n_in,
                              void* d_out, int out_size)
{
    const float* x  = (const float*)d_in[0];
    const float* Wq = (const float*)d_in[1];
    const float* bq = (const float*)d_in[2];
    const float* Wk = (const float*)d_in[3];
    const float* bk = (const float*)d_in[4];
    const float* Wv = (const float*)d_in[5];
    const float* bv = (const float*)d_in[6];
    float* out = (float*)d_out;

    const int SMEM_A = (32 * 113 + SZ * 114 + SZ) * (int)sizeof(float);  // 65984 B
    const int SMEM_B = 2 * 512 * 8 * (int)sizeof(ull);                   // 65536 B

    cudaFuncSetAttribute(qkv_kernel,  cudaFuncAttributeMaxDynamicSharedMemorySize, SMEM_A);
    cudaFuncSetAttribute(attn_kernel, cudaFuncAttributeMaxDynamicSharedMemorySize, SMEM_B);

    qkv_kernel<<<(NB * LQ) / 32, 256, SMEM_A>>>(x, Wq, bq, Wk, bk, Wv, bv);  // 256 CTAs

    attn_kernel<<<NB * HH * 2, 256, SMEM_B>>>(out);   // 256 CTAs, 2 per head
}